// round 2
// baseline (speedup 1.0000x reference)
#include <cuda_runtime.h>
#include <math.h>
#include <stdint.h>

// ============================================================================
// JAX threefry2x32, 20 rounds (5 four-round groups with key injections).
// ============================================================================
struct Keys { unsigned v[12]; };

__host__ __device__ inline void threefry2x32(unsigned k0, unsigned k1,
                                             unsigned x0, unsigned x1,
                                             unsigned &o0, unsigned &o1)
{
    unsigned ks2 = k0 ^ k1 ^ 0x1BD11BDAu;
#define TF_ROT(x, r) (((x) << (r)) | ((x) >> (32 - (r))))
#define TF_RND(r) { x0 += x1; x1 = TF_ROT(x1, r); x1 ^= x0; }
    x0 += k0; x1 += k1;
    TF_RND(13) TF_RND(15) TF_RND(26) TF_RND(6)
    x0 += k1;  x1 += ks2 + 1u;
    TF_RND(17) TF_RND(29) TF_RND(16) TF_RND(24)
    x0 += ks2; x1 += k0 + 2u;
    TF_RND(13) TF_RND(15) TF_RND(26) TF_RND(6)
    x0 += k0;  x1 += k1 + 3u;
    TF_RND(17) TF_RND(29) TF_RND(16) TF_RND(24)
    x0 += k1;  x1 += ks2 + 4u;
    TF_RND(13) TF_RND(15) TF_RND(26) TF_RND(6)
    x0 += ks2; x1 += k0 + 5u;
#undef TF_RND
#undef TF_ROT
    o0 = x0; o1 = x1;
}

// Partitionable-mode random bits for flat element index f (f < 2^32):
// counter = (hi32(f)=0, lo32(f)=f); 32-bit draw = lane0 ^ lane1.
__device__ __forceinline__ unsigned tf_bits(unsigned k0, unsigned k1, unsigned f)
{
    unsigned o0, o1;
    threefry2x32(k0, k1, 0u, f, o0, o1);
    return o0 ^ o1;
}

// JAX gumbel: u = uniform(key, minval=tiny, maxval=1); g = -log(-log(u))
// uniform bits path: f = bitcast((bits>>9)|0x3f800000) - 1; u = max(tiny, f*(1-tiny)+tiny)
// (1-tiny) == 1.0f exactly in fp32.
__device__ __forceinline__ float gumbel_f(unsigned bits)
{
    float f = __uint_as_float((bits >> 9) | 0x3f800000u) - 1.0f;
    float u = fmaxf(1.17549435e-38f, f + 1.17549435e-38f);
    return -logf(-logf(u));
}

// ============================================================================
// Warp-cooperative categorical sample + log_softmax + lpm.
// Each lane holds N candidate slots (score s[j], gumbel g[j], index tidx[j],
// mask mk[j]). Produces (warp-uniform): argmax(s+g) first-index ties,
// lp = s[a] - max(s) - log(sum exp(s - max)), lpm = (count(mk==0) > 1).
// ============================================================================
template <int N>
__device__ __forceinline__ void do_sample(const float* s, const float* g,
                                          const int* tidx, const float* mk,
                                          int &act, float &lp, float &lpmv)
{
    float zv = -INFINITY; int zi = 0x40000000; float zs = 0.0f;
    float m = -INFINITY;
#pragma unroll
    for (int j = 0; j < N; j++) {
        float z = s[j] + g[j];
        if (z > zv || (z == zv && tidx[j] < zi)) { zv = z; zi = tidx[j]; zs = s[j]; }
        m = fmaxf(m, s[j]);
    }
#pragma unroll
    for (int o = 16; o; o >>= 1) m = fmaxf(m, __shfl_xor_sync(0xffffffffu, m, o));
    float e = 0.0f;
#pragma unroll
    for (int j = 0; j < N; j++) e += expf(s[j] - m);
#pragma unroll
    for (int o = 16; o; o >>= 1) e += __shfl_xor_sync(0xffffffffu, e, o);
#pragma unroll
    for (int o = 16; o; o >>= 1) {
        float v2 = __shfl_xor_sync(0xffffffffu, zv, o);
        int   i2 = __shfl_xor_sync(0xffffffffu, zi, o);
        float s2 = __shfl_xor_sync(0xffffffffu, zs, o);
        if (v2 > zv || (v2 == zv && i2 < zi)) { zv = v2; zi = i2; zs = s2; }
    }
    int c = 0;
#pragma unroll
    for (int j = 0; j < N; j++) c += (mk[j] == 0.0f) ? 1 : 0;
    c = __reduce_add_sync(0xffffffffu, c);
    act = zi;
    lp = zs - m - logf(e);
    lpmv = (c > 1) ? 1.0f : 0.0f;
}

// ============================================================================
// Main kernel: one warp per batch row b; lane covers t = lane and t = lane+32.
// ============================================================================
__global__ void __launch_bounds__(256) pt_kernel(
    const float* __restrict__ order_mask,   // (B,7)
    const int*   __restrict__ budgets,      // (B,7,4)
    const float* __restrict__ tile_masks,   // (B,7,4,64)
    const int*   __restrict__ loop_ind_p,   // scalar
    const float* __restrict__ rbs_in,       // (B,)
    const int*   __restrict__ t2max_in,     // (B,)
    const float* __restrict__ mtemp_in,     // (B,)
    const int*   __restrict__ spmax_in,     // (B,)
    const int*   __restrict__ spmin_in,     // (B,)
    const float* __restrict__ order_logit,  // (B,7)
    const float* __restrict__ tile_logits,  // (B,4,64)
    const float* __restrict__ sp_logit,     // (B,64)
    float* __restrict__ out,
    int B, Keys keys)
{
    const int lane = threadIdx.x & 31;
    const int b = (int)((blockIdx.x * blockDim.x + threadIdx.x) >> 5);
    if (b >= B) return;

    const int li = loop_ind_p[0];

    float lp[6], lpmv[6];
    int tacts[4];
    int oact, spact;

    const int t0 = lane, t1 = lane + 32;
    const unsigned f0 = (unsigned)(b * 64 + t0);
    const unsigned f1 = f0 + 32u;
    int tidx2[2] = { t0, t1 };

    // ---------------- order sampling (T=7, keys[0]) ----------------
    {
        float s[1], mk[1], g1[1];
        int tidx1[1] = { lane };
        if (lane < 7) {
            unsigned bits = tf_bits(keys.v[0], keys.v[1], (unsigned)(b * 7 + lane));
            g1[0] = gumbel_f(bits);
            float m = order_mask[b * 7 + lane];
            mk[0] = m;
            s[0] = order_logit[b * 7 + lane] + m;
        } else { g1[0] = 0.0f; mk[0] = -1.0f; s[0] = -INFINITY; }
        do_sample<1>(s, g1, tidx1, mk, oact, lp[0], lpmv[0]);
    }

    // ---------------- sp_tile2 sampling (T=64, keys[1]) ----------------
    float base0, base1;
    {
        float g[2] = { gumbel_f(tf_bits(keys.v[2], keys.v[3], f0)),
                       gumbel_f(tf_bits(keys.v[2], keys.v[3], f1)) };
        int smx = spmax_in[b], smn = spmin_in[b];
        int basei = ((b * 7 + li) * 4 + 0) * 64;
        base0 = tile_masks[basei + t0];
        base1 = tile_masks[basei + t1];
        float s[2], mk[2];
        mk[0] = (t0 > smx || t0 < smn) ? -INFINITY : base0;
        mk[1] = (t1 > smx || t1 < smn) ? -INFINITY : base1;
        s[0] = sp_logit[b * 64 + t0] + mk[0];
        s[1] = sp_logit[b * 64 + t1] + mk[1];
        do_sample<2>(s, g, tidx2, mk, spact, lp[5], lpmv[5]);
    }

    // ---------------- tile2 sampling (p=0, T=64, keys[2]) ----------------
    {
        float g[2] = { gumbel_f(tf_bits(keys.v[4], keys.v[5], f0)),
                       gumbel_f(tf_bits(keys.v[4], keys.v[5], f1)) };
        int t2min = spact;
        int t2mx = min(t2max_in[b], t2min + (int)mtemp_in[b]);
        float s[2], mk[2];
        mk[0] = (t0 > t2mx || t0 < t2min) ? -INFINITY : base0;
        mk[1] = (t1 > t2mx || t1 < t2min) ? -INFINITY : base1;
        s[0] = tile_logits[(b * 4 + 0) * 64 + t0] + mk[0];
        s[1] = tile_logits[(b * 4 + 0) * 64 + t1] + mk[1];
        do_sample<2>(s, g, tidx2, mk, tacts[0], lp[1], lpmv[1]);
    }

    // ---------------- p = 1..3 chain (keys[3..5]) ----------------
    float rbs = rbs_in[b];
    int ta = tacts[0];
    const float primef[3] = { 2.0f, 3.0f, 5.0f };
    const float denom[3]  = { 1.5849625f,    // (float)np.log2(3)
                              2.321928f,     // (float)np.log2(5)
                              2.8073549f };  // (float)np.log2(7)
    for (int p = 1; p < 4; p++) {
        unsigned k0 = keys.v[2 * (2 + p)], k1 = keys.v[2 * (2 + p) + 1];
        float g[2] = { gumbel_f(tf_bits(k0, k1, f0)),
                       gumbel_f(tf_bits(k0, k1, f1)) };
        // rbs chain — replicate XLA op-for-op (all libdevice, all f32):
        rbs = rbs / powf(primef[p - 1], (float)ta);
        float tmf = logf(fmaxf(rbs, 1.0f)) * (1.0f / 0.69314718f); // jnp.log2 = log(x)/log(2)
        tmf = logf(fmaxf(rbs, 1.0f)) / 0.69314718f;                // keep exact div form
        tmf = tmf / denom[p - 1];                                  // / np.log2(prime)
        int tmax = (int)tmf;             // f32->s32 truncation toward zero
        tmax = max(0, min(tmax, 63));    // clip(0, T-1)
        tmax = min(tmax, budgets[(b * 7 + li) * 4 + p]);
        int mbase = ((b * 7 + li) * 4 + p) * 64;
        int lbase = (b * 4 + p) * 64;
        float s[2], mk[2];
        mk[0] = (t0 > tmax) ? -INFINITY : tile_masks[mbase + t0];
        mk[1] = (t1 > tmax) ? -INFINITY : tile_masks[mbase + t1];
        s[0] = tile_logits[lbase + t0] + mk[0];
        s[1] = tile_logits[lbase + t1] + mk[1];
        int a;
        do_sample<2>(s, g, tidx2, mk, a, lp[p + 1], lpmv[p + 1]);
        tacts[p] = a;
        ta = a;
    }

    // ---------------- write outputs ----------------
    // layout: order_action(B) | tile_actions(B,4) | sp_tile_actions(B,4)
    //         | log_probs(B,6) | log_prob_masks(B,6)   — all as f32
    if (lane == 0) {
        out[b] = (float)oact;
        float* ta_out = out + B;
        ta_out[b * 4 + 0] = (float)tacts[0];
        ta_out[b * 4 + 1] = (float)tacts[1];
        ta_out[b * 4 + 2] = (float)tacts[2];
        ta_out[b * 4 + 3] = (float)tacts[3];
        float* sp_out = out + 5 * B;
        sp_out[b * 4 + 0] = (float)spact;
        sp_out[b * 4 + 1] = 0.0f;
        sp_out[b * 4 + 2] = 0.0f;
        sp_out[b * 4 + 3] = 0.0f;
        float* lp_out = out + 9 * B;
        float* lm_out = out + 15 * B;
#pragma unroll
        for (int k = 0; k < 6; k++) {
            lp_out[b * 6 + k] = lp[k];
            lm_out[b * 6 + k] = lpmv[k];
        }
    }
}

// ============================================================================
// Launch: derive the 6 sampling keys = jax.random.split(jax.random.key(1), 6)
// in PARTITIONABLE mode: key[i] = threefry(k=(0,1), counter=(0, i)), both lanes.
// ============================================================================
extern "C" void kernel_launch(void* const* d_in, const int* in_sizes, int n_in,
                              void* d_out, int out_size)
{
    int B = in_sizes[6];  // remain_buffer_size is (B,)

    Keys keys;
    for (int i = 0; i < 6; i++) {
        unsigned o0, o1;
        threefry2x32(0u, 1u, 0u, (unsigned)i, o0, o1);
        keys.v[2 * i]     = o0;
        keys.v[2 * i + 1] = o1;
    }

    int threads = 256;
    int blocks = (B * 32 + threads - 1) / threads;

    pt_kernel<<<blocks, threads>>>(
        (const float*)d_in[1],   // order_mask
        (const int*)  d_in[2],   // tile_remain_budgets
        (const float*)d_in[3],   // tile_masks
        (const int*)  d_in[5],   // loop_ind
        (const float*)d_in[6],   // remain_buffer_size
        (const int*)  d_in[7],   // tile2_max
        (const float*)d_in[8],   // max_temporal_tile2
        (const int*)  d_in[9],   // sp_tile2_max
        (const int*)  d_in[10],  // sp_tile2_min
        (const float*)d_in[11],  // order_logit
        (const float*)d_in[12],  // tile_logits
        (const float*)d_in[13],  // sp_tile2_logit
        (float*)d_out, B, keys);
}

// round 3
// speedup vs baseline: 1.2276x; 1.2276x over previous
#include <cuda_runtime.h>
#include <math.h>
#include <stdint.h>

// ============================================================================
// JAX threefry2x32, 20 rounds (5 four-round groups with key injections).
// ============================================================================
struct Keys { unsigned v[12]; };

__host__ __device__ inline void threefry2x32(unsigned k0, unsigned k1,
                                             unsigned x0, unsigned x1,
                                             unsigned &o0, unsigned &o1)
{
    unsigned ks2 = k0 ^ k1 ^ 0x1BD11BDAu;
#define TF_ROT(x, r) (((x) << (r)) | ((x) >> (32 - (r))))
#define TF_RND(r) { x0 += x1; x1 = TF_ROT(x1, r); x1 ^= x0; }
    x0 += k0; x1 += k1;
    TF_RND(13) TF_RND(15) TF_RND(26) TF_RND(6)
    x0 += k1;  x1 += ks2 + 1u;
    TF_RND(17) TF_RND(29) TF_RND(16) TF_RND(24)
    x0 += ks2; x1 += k0 + 2u;
    TF_RND(13) TF_RND(15) TF_RND(26) TF_RND(6)
    x0 += k0;  x1 += k1 + 3u;
    TF_RND(17) TF_RND(29) TF_RND(16) TF_RND(24)
    x0 += k1;  x1 += ks2 + 4u;
    TF_RND(13) TF_RND(15) TF_RND(26) TF_RND(6)
    x0 += ks2; x1 += k0 + 5u;
#undef TF_RND
#undef TF_ROT
    o0 = x0; o1 = x1;
}

// Partitionable-mode random bits for flat element index f (f < 2^32):
// counter = (hi32(f)=0, lo32(f)=f); 32-bit draw = lane0 ^ lane1.
__device__ __forceinline__ unsigned tf_bits(unsigned k0, unsigned k1, unsigned f)
{
    unsigned o0, o1;
    threefry2x32(k0, k1, 0u, f, o0, o1);
    return o0 ^ o1;
}

// JAX gumbel — MUST stay bit-exact libdevice logf (gates integer argmax).
__device__ __forceinline__ float gumbel_f(unsigned bits)
{
    float f = __uint_as_float((bits >> 9) | 0x3f800000u) - 1.0f;
    float u = fmaxf(1.17549435e-38f, f + 1.17549435e-38f);
    return -logf(-logf(u));
}

// Order-preserving float<->uint bijection (monotonic incl. +-inf).
__device__ __forceinline__ unsigned ford(float f)
{
    unsigned b = __float_as_uint(f);
    return ((int)b < 0) ? ~b : (b | 0x80000000u);
}
__device__ __forceinline__ float funord(unsigned u)
{
    unsigned b = ((int)u < 0) ? (u & 0x7fffffffu) : ~u;
    return __uint_as_float(b);
}

// ============================================================================
// Warp-cooperative categorical sample + log_softmax + lpm.
// Argmax decision is exact (bit-compare on s+g, first-index ties, matching
// jnp.argmax); softmax lp uses fast-math (output tolerance 1e-3).
// ============================================================================
template <int N>
__device__ __forceinline__ void do_sample(const float* s, const float* g,
                                          const int* tidx, const float* mk,
                                          int &act, float &lp, float &lpmv)
{
    float zv, m; int zi;
    if (N == 2) {
        float z0 = s[0] + g[0], z1 = s[1] + g[1];
        bool hi = (z1 > z0);              // strict: first-index tie-break
        zv = hi ? z1 : z0;
        zi = hi ? tidx[1] : tidx[0];
        m  = fmaxf(s[0], s[1]);
    } else {
        zv = s[0] + g[0]; zi = tidx[0]; m = s[0];
    }

    unsigned zk = ford(zv);
    unsigned zmax = __reduce_max_sync(0xffffffffu, zk);
    act = __reduce_min_sync(0xffffffffu, (zk == zmax) ? zi : 0x7fffffff);

    float mmax = funord(__reduce_max_sync(0xffffffffu, ford(m)));

    float e = __expf(s[0] - mmax);
    if (N == 2) e += __expf(s[1] - mmax);
#pragma unroll
    for (int o = 16; o; o >>= 1) e += __shfl_xor_sync(0xffffffffu, e, o);

    float zs;
    if (N == 2) {
        float ssel = (act >= 32) ? s[1] : s[0];
        zs = __shfl_sync(0xffffffffu, ssel, act & 31);
    } else {
        zs = __shfl_sync(0xffffffffu, s[0], act);
    }

    int c = 0;
#pragma unroll
    for (int j = 0; j < N; j++) c += (mk[j] == 0.0f) ? 1 : 0;
    c = __reduce_add_sync(0xffffffffu, c);

    lp = zs - mmax - __logf(e);
    lpmv = (c > 1) ? 1.0f : 0.0f;
}

// ============================================================================
// Main kernel: one warp per batch row b; lane covers t = lane and t = lane+32.
// ============================================================================
__global__ void __launch_bounds__(256) pt_kernel(
    const float* __restrict__ order_mask,   // (B,7)
    const int*   __restrict__ budgets,      // (B,7,4)
    const float* __restrict__ tile_masks,   // (B,7,4,64)
    const int*   __restrict__ loop_ind_p,   // scalar
    const float* __restrict__ rbs_in,       // (B,)
    const int*   __restrict__ t2max_in,     // (B,)
    const float* __restrict__ mtemp_in,     // (B,)
    const int*   __restrict__ spmax_in,     // (B,)
    const int*   __restrict__ spmin_in,     // (B,)
    const float* __restrict__ order_logit,  // (B,7)
    const float* __restrict__ tile_logits,  // (B,4,64)
    const float* __restrict__ sp_logit,     // (B,64)
    float* __restrict__ out,
    int B, Keys keys)
{
    const int lane = threadIdx.x & 31;
    const int b = (int)((blockIdx.x * blockDim.x + threadIdx.x) >> 5);
    if (b >= B) return;

    const int li = loop_ind_p[0];

    float lp[6], lpmv[6];
    int tacts[4];
    int oact, spact;

    const int t0 = lane, t1 = lane + 32;
    const unsigned f0 = (unsigned)(b * 64 + t0);
    const unsigned f1 = f0 + 32u;
    int tidx2[2] = { t0, t1 };

    // ---------------- order sampling (T=7, keys[0]) ----------------
    {
        float s[1], mk[1], g1[1];
        int tidx1[1] = { lane };
        if (lane < 7) {
            unsigned bits = tf_bits(keys.v[0], keys.v[1], (unsigned)(b * 7 + lane));
            g1[0] = gumbel_f(bits);
            float m = order_mask[b * 7 + lane];
            mk[0] = m;
            s[0] = order_logit[b * 7 + lane] + m;
        } else { g1[0] = 0.0f; mk[0] = -1.0f; s[0] = -INFINITY; }
        do_sample<1>(s, g1, tidx1, mk, oact, lp[0], lpmv[0]);
    }

    // ---------------- sp_tile2 sampling (T=64, keys[1]) ----------------
    float base0, base1;
    {
        float g[2] = { gumbel_f(tf_bits(keys.v[2], keys.v[3], f0)),
                       gumbel_f(tf_bits(keys.v[2], keys.v[3], f1)) };
        int smx = spmax_in[b], smn = spmin_in[b];
        int basei = ((b * 7 + li) * 4 + 0) * 64;
        base0 = tile_masks[basei + t0];
        base1 = tile_masks[basei + t1];
        float s[2], mk[2];
        mk[0] = (t0 > smx || t0 < smn) ? -INFINITY : base0;
        mk[1] = (t1 > smx || t1 < smn) ? -INFINITY : base1;
        s[0] = sp_logit[b * 64 + t0] + mk[0];
        s[1] = sp_logit[b * 64 + t1] + mk[1];
        do_sample<2>(s, g, tidx2, mk, spact, lp[5], lpmv[5]);
    }

    // ---------------- tile2 sampling (p=0, T=64, keys[2]) ----------------
    {
        float g[2] = { gumbel_f(tf_bits(keys.v[4], keys.v[5], f0)),
                       gumbel_f(tf_bits(keys.v[4], keys.v[5], f1)) };
        int t2min = spact;
        int t2mx = min(t2max_in[b], t2min + (int)mtemp_in[b]);
        float s[2], mk[2];
        mk[0] = (t0 > t2mx || t0 < t2min) ? -INFINITY : base0;
        mk[1] = (t1 > t2mx || t1 < t2min) ? -INFINITY : base1;
        s[0] = tile_logits[(b * 4 + 0) * 64 + t0] + mk[0];
        s[1] = tile_logits[(b * 4 + 0) * 64 + t1] + mk[1];
        do_sample<2>(s, g, tidx2, mk, tacts[0], lp[1], lpmv[1]);
    }

    // ---------------- p = 1..3 chain (keys[3..5]) ----------------
    float rbs = rbs_in[b];
    int ta = tacts[0];
    const float primef[3] = { 2.0f, 3.0f, 5.0f };
    const float denom[3]  = { 1.5849625f,    // (float)np.log2(3)
                              2.321928f,     // (float)np.log2(5)
                              2.8073549f };  // (float)np.log2(7)
    for (int p = 1; p < 4; p++) {
        unsigned k0 = keys.v[2 * (2 + p)], k1 = keys.v[2 * (2 + p) + 1];
        float g[2] = { gumbel_f(tf_bits(k0, k1, f0)),
                       gumbel_f(tf_bits(k0, k1, f1)) };
        // rbs chain — byte-identical to the passing R2 version:
        rbs = rbs / powf(primef[p - 1], (float)ta);
        float tmf = logf(fmaxf(rbs, 1.0f)) / 0.69314718f;  // jnp.log2
        tmf = tmf / denom[p - 1];                          // / np.log2(prime)
        int tmax = (int)tmf;             // f32->s32 truncation toward zero
        tmax = max(0, min(tmax, 63));    // clip(0, T-1)
        tmax = min(tmax, budgets[(b * 7 + li) * 4 + p]);
        int mbase = ((b * 7 + li) * 4 + p) * 64;
        int lbase = (b * 4 + p) * 64;
        float s[2], mk[2];
        mk[0] = (t0 > tmax) ? -INFINITY : tile_masks[mbase + t0];
        mk[1] = (t1 > tmax) ? -INFINITY : tile_masks[mbase + t1];
        s[0] = tile_logits[lbase + t0] + mk[0];
        s[1] = tile_logits[lbase + t1] + mk[1];
        int a;
        do_sample<2>(s, g, tidx2, mk, a, lp[p + 1], lpmv[p + 1]);
        tacts[p] = a;
        ta = a;
    }

    // ---------------- write outputs ----------------
    // layout: order_action(B) | tile_actions(B,4) | sp_tile_actions(B,4)
    //         | log_probs(B,6) | log_prob_masks(B,6)   — all as f32
    if (lane == 0) {
        out[b] = (float)oact;
        float* ta_out = out + B;
        ta_out[b * 4 + 0] = (float)tacts[0];
        ta_out[b * 4 + 1] = (float)tacts[1];
        ta_out[b * 4 + 2] = (float)tacts[2];
        ta_out[b * 4 + 3] = (float)tacts[3];
        float* sp_out = out + 5 * B;
        sp_out[b * 4 + 0] = (float)spact;
        sp_out[b * 4 + 1] = 0.0f;
        sp_out[b * 4 + 2] = 0.0f;
        sp_out[b * 4 + 3] = 0.0f;
        float* lp_out = out + 9 * B;
        float* lm_out = out + 15 * B;
#pragma unroll
        for (int k = 0; k < 6; k++) {
            lp_out[b * 6 + k] = lp[k];
            lm_out[b * 6 + k] = lpmv[k];
        }
    }
}

// ============================================================================
// Launch: keys = jax.random.split(jax.random.key(1), 6), partitionable mode.
// ============================================================================
extern "C" void kernel_launch(void* const* d_in, const int* in_sizes, int n_in,
                              void* d_out, int out_size)
{
    int B = in_sizes[6];  // remain_buffer_size is (B,)

    Keys keys;
    for (int i = 0; i < 6; i++) {
        unsigned o0, o1;
        threefry2x32(0u, 1u, 0u, (unsigned)i, o0, o1);
        keys.v[2 * i]     = o0;
        keys.v[2 * i + 1] = o1;
    }

    int threads = 256;
    int blocks = (B * 32 + threads - 1) / threads;

    pt_kernel<<<blocks, threads>>>(
        (const float*)d_in[1],   // order_mask
        (const int*)  d_in[2],   // tile_remain_budgets
        (const float*)d_in[3],   // tile_masks
        (const int*)  d_in[5],   // loop_ind
        (const float*)d_in[6],   // remain_buffer_size
        (const int*)  d_in[7],   // tile2_max
        (const float*)d_in[8],   // max_temporal_tile2
        (const int*)  d_in[9],   // sp_tile2_max
        (const int*)  d_in[10],  // sp_tile2_min
        (const float*)d_in[11],  // order_logit
        (const float*)d_in[12],  // tile_logits
        (const float*)d_in[13],  // sp_tile2_logit
        (float*)d_out, B, keys);
}

// round 5
// speedup vs baseline: 1.4579x; 1.1876x over previous
#include <cuda_runtime.h>
#include <math.h>
#include <stdint.h>

// ============================================================================
// JAX threefry2x32, 20 rounds (5 four-round groups with key injections).
// ============================================================================
struct Keys { unsigned v[12]; };

__host__ __device__ inline void threefry2x32(unsigned k0, unsigned k1,
                                             unsigned x0, unsigned x1,
                                             unsigned &o0, unsigned &o1)
{
    unsigned ks2 = k0 ^ k1 ^ 0x1BD11BDAu;
#define TF_ROT(x, r) (((x) << (r)) | ((x) >> (32 - (r))))
#define TF_RND(r) { x0 += x1; x1 = TF_ROT(x1, r); x1 ^= x0; }
    x0 += k0; x1 += k1;
    TF_RND(13) TF_RND(15) TF_RND(26) TF_RND(6)
    x0 += k1;  x1 += ks2 + 1u;
    TF_RND(17) TF_RND(29) TF_RND(16) TF_RND(24)
    x0 += ks2; x1 += k0 + 2u;
    TF_RND(13) TF_RND(15) TF_RND(26) TF_RND(6)
    x0 += k0;  x1 += k1 + 3u;
    TF_RND(17) TF_RND(29) TF_RND(16) TF_RND(24)
    x0 += k1;  x1 += ks2 + 4u;
    TF_RND(13) TF_RND(15) TF_RND(26) TF_RND(6)
    x0 += ks2; x1 += k0 + 5u;
#undef TF_RND
#undef TF_ROT
    o0 = x0; o1 = x1;
}

// Partitionable-mode random bits: counter = (0, f); draw = lane0 ^ lane1.
__device__ __forceinline__ unsigned tf_bits(unsigned k0, unsigned k1, unsigned f)
{
    unsigned o0, o1;
    threefry2x32(k0, k1, 0u, f, o0, o1);
    return o0 ^ o1;
}

// JAX gumbel — MUST stay bit-exact libdevice logf (gates integer argmax).
__device__ __forceinline__ float gumbel_f(unsigned bits)
{
    float f = __uint_as_float((bits >> 9) | 0x3f800000u) - 1.0f;
    float u = fmaxf(1.17549435e-38f, f + 1.17549435e-38f);
    return -logf(-logf(u));
}

// Order-preserving float->uint bijection (monotonic incl. +-inf).
__device__ __forceinline__ unsigned ford(float f)
{
    unsigned b = __float_as_uint(f);
    return ((int)b < 0) ? ~b : (b | 0x80000000u);
}
__device__ __forceinline__ float funord(unsigned u)
{
    unsigned b = ((int)u < 0) ? (u & 0x7fffffffu) : ~u;
    return __uint_as_float(b);
}

// ============================================================================
// Warp sample over 64 slots: lane holds t0=2*lane, t1=2*lane+1.
// Argmax exact (bit-compare, first-index ties == jnp.argmax); lp fast-math.
// ============================================================================
__device__ __forceinline__ void sample64(float s0, float s1, float g0, float g1,
                                         float mk0, float mk1, int lane,
                                         int &act, float &lp, float &lpmv)
{
    float z0 = s0 + g0, z1 = s1 + g1;
    bool hi = (z1 > z0);                       // strict: first-index ties
    float zv = hi ? z1 : z0;
    int   zi = 2 * lane + (hi ? 1 : 0);
    float m  = fmaxf(s0, s1);

    unsigned zk = ford(zv);
    unsigned zmax = __reduce_max_sync(0xffffffffu, zk);
    act = __reduce_min_sync(0xffffffffu, (zk == zmax) ? zi : 0x7fffffff);

    float mmax = funord(__reduce_max_sync(0xffffffffu, ford(m)));

    float e = __expf(s0 - mmax) + __expf(s1 - mmax);
    int ei = (int)(e * 16777216.0f);           // 2^24 scale; sum < 2^31
    int esum = __reduce_add_sync(0xffffffffu, ei);
    float ef = (float)esum * 5.9604644775390625e-08f;  // / 2^24

    float ssel = (act & 1) ? s1 : s0;
    float zs = __shfl_sync(0xffffffffu, ssel, act >> 1);

    int c = ((mk0 == 0.0f) ? 1 : 0) + ((mk1 == 0.0f) ? 1 : 0);
    c = __reduce_add_sync(0xffffffffu, c);

    lp = zs - mmax - __logf(ef);
    lpmv = (c > 1) ? 1.0f : 0.0f;
}

// ============================================================================
// Main kernel: one warp per batch row b.
// ============================================================================
__global__ void __launch_bounds__(256) pt_kernel(
    const float* __restrict__ order_mask,   // (B,7)
    const int*   __restrict__ budgets,      // (B,7,4)
    const float* __restrict__ tile_masks,   // (B,7,4,64)
    const int*   __restrict__ loop_ind_p,   // scalar
    const float* __restrict__ rbs_in,       // (B,)
    const int*   __restrict__ t2max_in,     // (B,)
    const float* __restrict__ mtemp_in,     // (B,)
    const int*   __restrict__ spmax_in,     // (B,)
    const int*   __restrict__ spmin_in,     // (B,)
    const float* __restrict__ order_logit,  // (B,7)
    const float* __restrict__ tile_logits,  // (B,4,64)
    const float* __restrict__ sp_logit,     // (B,64)
    float* __restrict__ out,
    int B, Keys keys)
{
    const int lane = threadIdx.x & 31;
    const int b = (int)((blockIdx.x * blockDim.x + threadIdx.x) >> 5);
    if (b >= B) return;

    const int li = loop_ind_p[0];

    const int t0 = 2 * lane, t1 = t0 + 1;
    const unsigned f0 = (unsigned)(b * 64 + t0);
    const unsigned f1 = f0 + 1u;

    // ---- hoisted threefry: all 11 evals upfront (pure int, max ILP) ----
    unsigned bo  = tf_bits(keys.v[0],  keys.v[1],  (unsigned)(b * 7 + (lane < 7 ? lane : 0)));
    unsigned bs0 = tf_bits(keys.v[2],  keys.v[3],  f0);
    unsigned bs1 = tf_bits(keys.v[2],  keys.v[3],  f1);
    unsigned bt0[4], bt1[4];
#pragma unroll
    for (int p = 0; p < 4; p++) {
        bt0[p] = tf_bits(keys.v[4 + 2 * p], keys.v[5 + 2 * p], f0);
        bt1[p] = tf_bits(keys.v[4 + 2 * p], keys.v[5 + 2 * p], f1);
    }

    float lp[6], lpmv[6];
    int tacts[4];
    int oact, spact;

    // ---------------- order sampling (T=7, keys[0]) ----------------
    {
        float s, mk, g1v;
        if (lane < 7) {
            g1v = gumbel_f(bo);
            mk = order_mask[b * 7 + lane];
            s = order_logit[b * 7 + lane] + mk;
        } else { g1v = 0.0f; mk = -1.0f; s = -INFINITY; }

        float zv = s + g1v;
        unsigned zk = ford(zv);
        unsigned zmax = __reduce_max_sync(0xffffffffu, zk);
        oact = __reduce_min_sync(0xffffffffu, (zk == zmax) ? lane : 0x7fffffff);
        float mmax = funord(__reduce_max_sync(0xffffffffu, ford(s)));
        float e = __expf(s - mmax);
        int ei = (int)(e * 16777216.0f);
        int esum = __reduce_add_sync(0xffffffffu, ei);
        float ef = (float)esum * 5.9604644775390625e-08f;
        float zs = __shfl_sync(0xffffffffu, s, oact);
        int c = (mk == 0.0f) ? 1 : 0;
        c = __reduce_add_sync(0xffffffffu, c);
        lp[0] = zs - mmax - __logf(ef);
        lpmv[0] = (c > 1) ? 1.0f : 0.0f;
    }

    // ---------------- sp_tile2 sampling (T=64, keys[1]) ----------------
    float2 base;
    {
        float g0 = gumbel_f(bs0), g1 = gumbel_f(bs1);
        int smx = spmax_in[b], smn = spmin_in[b];
        int basei = ((b * 7 + li) * 4 + 0) * 64;
        base = *reinterpret_cast<const float2*>(tile_masks + basei + t0);
        float2 lg = *reinterpret_cast<const float2*>(sp_logit + b * 64 + t0);
        float mk0 = (t0 > smx || t0 < smn) ? -INFINITY : base.x;
        float mk1 = (t1 > smx || t1 < smn) ? -INFINITY : base.y;
        sample64(lg.x + mk0, lg.y + mk1, g0, g1, mk0, mk1, lane,
                 spact, lp[5], lpmv[5]);
    }

    // ---------------- tile2 sampling (p=0, keys[2]) ----------------
    {
        float g0 = gumbel_f(bt0[0]), g1 = gumbel_f(bt1[0]);
        int t2min = spact;
        int t2mx = min(t2max_in[b], t2min + (int)mtemp_in[b]);
        float2 lg = *reinterpret_cast<const float2*>(tile_logits + (b * 4 + 0) * 64 + t0);
        float mk0 = (t0 > t2mx || t0 < t2min) ? -INFINITY : base.x;
        float mk1 = (t1 > t2mx || t1 < t2min) ? -INFINITY : base.y;
        sample64(lg.x + mk0, lg.y + mk1, g0, g1, mk0, mk1, lane,
                 tacts[0], lp[1], lpmv[1]);
    }

    // ---------------- p = 1..3 chain (keys[3..5]) ----------------
    float rbs = rbs_in[b];
    int ta = tacts[0];
    const float primef[3] = { 2.0f, 3.0f, 5.0f };
    const float denom[3]  = { 1.5849625f,    // (float)np.log2(3)
                              2.321928f,     // (float)np.log2(5)
                              2.8073549f };  // (float)np.log2(7)
#pragma unroll
    for (int p = 1; p < 4; p++) {
        float g0 = gumbel_f(bt0[p]), g1 = gumbel_f(bt1[p]);
        // rbs chain — byte-identical to the passing R2/R3 version:
        rbs = rbs / powf(primef[p - 1], (float)ta);
        float tmf = logf(fmaxf(rbs, 1.0f)) / 0.69314718f;  // jnp.log2
        tmf = tmf / denom[p - 1];                          // / np.log2(prime)
        int tmax = (int)tmf;             // f32->s32 truncation toward zero
        tmax = max(0, min(tmax, 63));    // clip(0, T-1)
        tmax = min(tmax, budgets[(b * 7 + li) * 4 + p]);
        int mbase = ((b * 7 + li) * 4 + p) * 64;
        int lbase = (b * 4 + p) * 64;
        float2 tm = *reinterpret_cast<const float2*>(tile_masks + mbase + t0);
        float2 lg = *reinterpret_cast<const float2*>(tile_logits + lbase + t0);
        float mk0 = (t0 > tmax) ? -INFINITY : tm.x;
        float mk1 = (t1 > tmax) ? -INFINITY : tm.y;
        int a;
        sample64(lg.x + mk0, lg.y + mk1, g0, g1, mk0, mk1, lane,
                 a, lp[p + 1], lpmv[p + 1]);
        tacts[p] = a;
        ta = a;
    }

    // ---------------- write outputs ----------------
    // layout: order_action(B) | tile_actions(B,4) | sp_tile_actions(B,4)
    //         | log_probs(B,6) | log_prob_masks(B,6)   — all as f32
    if (lane == 0) {
        out[b] = (float)oact;
        float* ta_out = out + B;
        ta_out[b * 4 + 0] = (float)tacts[0];
        ta_out[b * 4 + 1] = (float)tacts[1];
        ta_out[b * 4 + 2] = (float)tacts[2];
        ta_out[b * 4 + 3] = (float)tacts[3];
        float* sp_out = out + 5 * B;
        sp_out[b * 4 + 0] = (float)spact;
        sp_out[b * 4 + 1] = 0.0f;
        sp_out[b * 4 + 2] = 0.0f;
        sp_out[b * 4 + 3] = 0.0f;
        float* lp_out = out + 9 * B;
        float* lm_out = out + 15 * B;
#pragma unroll
        for (int k = 0; k < 6; k++) {
            lp_out[b * 6 + k] = lp[k];
            lm_out[b * 6 + k] = lpmv[k];
        }
    }
}

// ============================================================================
// Launch: keys = jax.random.split(jax.random.key(1), 6), partitionable mode.
// ============================================================================
extern "C" void kernel_launch(void* const* d_in, const int* in_sizes, int n_in,
                              void* d_out, int out_size)
{
    int B = in_sizes[6];  // remain_buffer_size is (B,)

    Keys keys;
    for (int i = 0; i < 6; i++) {
        unsigned o0, o1;
        threefry2x32(0u, 1u, 0u, (unsigned)i, o0, o1);
        keys.v[2 * i]     = o0;
        keys.v[2 * i + 1] = o1;
    }

    int threads = 256;
    int blocks = (B * 32 + threads - 1) / threads;

    pt_kernel<<<blocks, threads>>>(
        (const float*)d_in[1],   // order_mask
        (const int*)  d_in[2],   // tile_remain_budgets
        (const float*)d_in[3],   // tile_masks
        (const int*)  d_in[5],   // loop_ind
        (const float*)d_in[6],   // remain_buffer_size
        (const int*)  d_in[7],   // tile2_max
        (const float*)d_in[8],   // max_temporal_tile2
        (const int*)  d_in[9],   // sp_tile2_max
        (const int*)  d_in[10],  // sp_tile2_min
        (const float*)d_in[11],  // order_logit
        (const float*)d_in[12],  // tile_logits
        (const float*)d_in[13],  // sp_tile2_logit
        (float*)d_out, B, keys);
}